// round 11
// baseline (speedup 1.0000x reference)
#include <cuda_runtime.h>
#include <cstdint>
#include <math.h>

#define S_LEN  8192
#define DMODEL 2048
#define HQN    16
#define HKVN   4
#define HD     128
#define WIN    512
#define KVDIM  (HKVN * HD)        /* 512 */
#define QDIM   (HQN * HD)         /* 2048 */
#define NQKV   3072               /* concatenated QKV output cols */

// ---- GEMM tiling: 128x128 tile, K=16 chunks, 6 stages, 2 chunks per barrier ----
#define ASTR   20                 /* A smem row stride (floats) */
#define BSTR   136                /* B smem row stride (floats) */
#define ASTG   (128 * ASTR)       /* 2560 floats per A stage */
#define BSTG   (16 * BSTR)        /* 2176 floats per B stage */
#define NSTAGE 6
#define GEMM_SMEM_BYTES (NSTAGE * (ASTG + BSTG) * 4)   /* 113664 B; 2 CTAs/SM */

// ---------------- scratch (static device globals; no allocation) ----------------
__device__ float g_q[S_LEN * QDIM];                         // 64 MB (tf32)
__device__ float g_kpad[(S_LEN + WIN) * KVDIM];             // 17 MB (rows 0..511 zero)
__device__ float g_vpad[(S_LEN + WIN) * KVDIM];             // 17 MB
__device__ float g_attn[S_LEN * QDIM];                      // 64 MB
// tf32-rounded inputs
__device__ float g_h[S_LEN * DMODEL];                       // 64 MB
__device__ float g_wqkv[DMODEL * NQKV];                     // 24 MB (Wq|Wk|Wv concat)
__device__ float g_wo[QDIM * DMODEL];                       // 16 MB

// ---------------- helpers ----------------
__device__ __forceinline__ float to_tf32(float x) {
    uint32_t u;
    asm("cvt.rna.tf32.f32 %0, %1;" : "=r"(u) : "f"(x));
    return __uint_as_float(u);
}
__device__ __forceinline__ uint32_t smem_u32(const void* p) {
    uint32_t a;
    asm("{ .reg .u64 t; cvta.to.shared.u64 t, %1; cvt.u32.u64 %0, t; }" : "=r"(a) : "l"(p));
    return a;
}
__device__ __forceinline__ void cp16(uint32_t dst, const void* src) {
    asm volatile("cp.async.cg.shared.global [%0], [%1], 16;" :: "r"(dst), "l"(src) : "memory");
}
#define CP_COMMIT() asm volatile("cp.async.commit_group;" ::: "memory")
__device__ __forceinline__ void mma_tf32(float* c, const uint32_t* a, const uint32_t* b) {
    asm volatile(
        "mma.sync.aligned.m16n8k8.row.col.f32.tf32.tf32.f32 "
        "{%0,%1,%2,%3}, {%4,%5,%6,%7}, {%8,%9}, {%0,%1,%2,%3};"
        : "+f"(c[0]), "+f"(c[1]), "+f"(c[2]), "+f"(c[3])
        : "r"(a[0]), "r"(a[1]), "r"(a[2]), "r"(a[3]), "r"(b[0]), "r"(b[1]));
}

// ---------------- mma.sync tf32 128x128 GEMM tile, NN, pair-pipelined 6 stages ----------------
// C tile rows by*128.., cols 0..127 of (C = A * B[:, bcol:bcol+128]); C pre-offset to its col.
// ROUND: round outputs to tf32 (when C feeds a later MMA as operand)
template <bool ROUND>
__device__ __forceinline__ void gemm_mma(
    const float* __restrict__ A, int lda,
    const float* __restrict__ B, int ldb, int bcol,
    float* __restrict__ C, int ldc,
    int K, int by)
{
    extern __shared__ float smdyn[];
    float* As = smdyn;                       // NSTAGE * ASTG floats
    float* Bs = smdyn + NSTAGE * ASTG;       // NSTAGE * BSTG floats

    const int tid = threadIdx.x;
    const int lane = tid & 31;
    const int w = tid >> 5;
    const int wm = (w & 3) * 32;
    const int wn = (w >> 2) * 64;

    const float* Ag = A + (size_t)(by * 128) * lda;
    const float* Bg = B + bcol;

    const uint32_t as_base = smem_u32(As);
    const uint32_t bs_base = smem_u32(Bs);

    const int arow = tid >> 1;
    const int acol = (tid & 1) * 8;
    const int bid = tid * 2;
    const int brow = bid >> 5;
    const int bcol2 = (bid & 31) * 4;

    float acc[2][8][4];
#pragma unroll
    for (int mt = 0; mt < 2; ++mt)
#pragma unroll
        for (int nt = 0; nt < 8; ++nt)
#pragma unroll
            for (int i = 0; i < 4; ++i) acc[mt][nt][i] = 0.f;

    const int npair = K >> 5;                // K=2048 -> 64 pairs of 16-chunks

    // one chunk load into stage st
    auto load_chunk = [&](int c, int st) {
        const int k0 = c << 4;
        {
            const float* src = Ag + (size_t)arow * lda + k0 + acol;
            uint32_t d = as_base + (uint32_t)(st * ASTG + arow * ASTR + acol) * 4u;
            cp16(d, src);
            cp16(d + 16, src + 4);
        }
        {
            const float* src = Bg + (size_t)(k0 + brow) * ldb + bcol2;
            uint32_t d = bs_base + (uint32_t)(st * BSTG + brow * BSTR + bcol2) * 4u;
            cp16(d, src);
            cp16(d + 16, src + 4);
        }
    };
    // pair p -> chunks 2p, 2p+1 -> stages (2p)%6, (2p+1)%6; ONE commit group per pair
    auto issue_pair = [&](int p) {
        const int s0 = (2 * p) % NSTAGE;
        load_chunk(2 * p, s0);
        load_chunk(2 * p + 1, s0 + 1);       // (2p)%6 is even -> +1 stays in range
        CP_COMMIT();
    };

    issue_pair(0);
    if (npair > 1) issue_pair(1);

    const int r = lane >> 2, cc = lane & 3;
    for (int p = 0; p < npair; ++p) {
        asm volatile("cp.async.wait_group 1;" ::: "memory");
        __syncthreads();

        const int sbase2 = (2 * p) % NSTAGE;
#pragma unroll
        for (int half = 0; half < 2; ++half) {
            const float* Asb = As + (sbase2 + half) * ASTG;
            const float* Bsb = Bs + (sbase2 + half) * BSTG;
#pragma unroll
            for (int ks = 0; ks < 2; ++ks) {
                uint32_t a[2][4], b[8][2];
#pragma unroll
                for (int mt = 0; mt < 2; ++mt) {
                    const float* ab = Asb + (wm + mt * 16 + r) * ASTR + ks * 8 + cc;
                    a[mt][0] = __float_as_uint(ab[0]);
                    a[mt][1] = __float_as_uint(ab[8 * ASTR]);
                    a[mt][2] = __float_as_uint(ab[4]);
                    a[mt][3] = __float_as_uint(ab[8 * ASTR + 4]);
                }
#pragma unroll
                for (int nt = 0; nt < 8; ++nt) {
                    const float* bb = Bsb + (ks * 8 + cc) * BSTR + wn + nt * 8 + r;
                    b[nt][0] = __float_as_uint(bb[0]);
                    b[nt][1] = __float_as_uint(bb[4 * BSTR]);
                }
#pragma unroll
                for (int mt = 0; mt < 2; ++mt)
#pragma unroll
                    for (int nt = 0; nt < 8; ++nt)
                        mma_tf32(acc[mt][nt], a[mt], b[nt]);
            }
        }

        // refill stages freed in iteration p-1 (all readers passed this iteration's sync)
        if (p + 2 < npair) issue_pair(p + 2);
        else CP_COMMIT();                    // keep group count exact at the tail
    }

    float* Cb = C + (size_t)(by * 128) * ldc;
    const int c2 = (lane & 3) * 2;
#pragma unroll
    for (int mt = 0; mt < 2; ++mt) {
        const int row = wm + mt * 16 + r;
#pragma unroll
        for (int nt = 0; nt < 8; ++nt) {
            const int col = wn + nt * 8 + c2;
            float v0 = acc[mt][nt][0], v1 = acc[mt][nt][1];
            float v2 = acc[mt][nt][2], v3 = acc[mt][nt][3];
            if (ROUND) { v0 = to_tf32(v0); v1 = to_tf32(v1); v2 = to_tf32(v2); v3 = to_tf32(v3); }
            *(float2*)(Cb + (size_t)row * ldc + col) = make_float2(v0, v1);
            *(float2*)(Cb + (size_t)(row + 8) * ldc + col) = make_float2(v2, v3);
        }
    }
}

// ---------------- merged QKV projection: one GEMM vs concatenated weights ----------------
__global__ __launch_bounds__(256, 2)
void qkvproj_mma(void) {
    const int bx = blockIdx.x, by = blockIdx.y;
    float* C;
    int ldc;
    if (bx < 16)      { C = g_q + bx * 128;                                    ldc = QDIM; }
    else if (bx < 20) { C = g_kpad + (size_t)WIN * KVDIM + (bx - 16) * 128;    ldc = KVDIM; }
    else              { C = g_vpad + (size_t)WIN * KVDIM + (bx - 20) * 128;    ldc = KVDIM; }
    gemm_mma<true>(g_h, DMODEL, g_wqkv, NQKV, bx * 128, C, ldc, DMODEL, by);
}
__global__ __launch_bounds__(256, 2)
void oproj_mma(float* __restrict__ out) {
    gemm_mma<false>(g_attn, QDIM, g_wo, DMODEL, blockIdx.x * 128,
                    out + blockIdx.x * 128, DMODEL, QDIM, blockIdx.y);
}

// ---------------- fused flash attention (band window, online softmax) ----------------
// grid (64 qblocks, 16 heads), 256 threads (8 warps x 16 query rows)
#define QSTR 132
#define KSTR 132
#define VSTR 136
#define SM_Q 0
#define SM_K (128 * QSTR)                       /* 16896 */
#define SM_V (SM_K + 2 * 64 * KSTR)             /* 33792 floats after SM_K */
#define FA_SMEM_FLOATS (SM_V + 2 * 64 * VSTR)   /* 51200 floats */
#define FA_SMEM_BYTES  (FA_SMEM_FLOATS * 4)     /* 204800 B */
#define NCH 10

__global__ __launch_bounds__(256, 1)
void fattn_kernel() {
    extern __shared__ float sm[];
    const int qb = blockIdx.x, h = blockIdx.y;
    const int tid = threadIdx.x, lane = tid & 31, w = tid >> 5;
    const uint32_t sbase = smem_u32(sm);

    const float* Qg = g_q + (size_t)(qb * 128) * QDIM + h * HD;
    const float* Kg = g_kpad + (size_t)(qb * 128) * KVDIM + (h >> 2) * HD;
    const float* Vg = g_vpad + (size_t)(qb * 128) * KVDIM + (h >> 2) * HD;

    const int qr = tid >> 1, qh = tid & 1;   // Q loader: row, half
    const int kr = tid >> 2, kq = tid & 3;   // K/V loader: row, quarter

    auto issueQ = [&]() {
        const float* src = Qg + (size_t)qr * QDIM + qh * 64;
        uint32_t d = sbase + (uint32_t)(qr * QSTR + qh * 64) * 4u;
#pragma unroll
        for (int j = 0; j < 8; ++j) {
            cp16(d + j * 32, src + j * 8);
            cp16(d + j * 32 + 16, src + j * 8 + 4);
        }
    };
    auto issueKV = [&](int c) {
        const int s = c & 1;
        const float* ks = Kg + (size_t)(c * 64 + kr) * KVDIM + kq * 32;
        uint32_t kd = sbase + (uint32_t)(SM_K + s * 64 * KSTR + kr * KSTR + kq * 32) * 4u;
#pragma unroll
        for (int j = 0; j < 8; ++j) cp16(kd + j * 16, ks + j * 4);
        const float* vs = Vg + (size_t)(c * 64 + kr) * KVDIM + kq * 32;
        uint32_t vd = sbase + (uint32_t)(SM_V + s * 64 * VSTR + kr * VSTR + kq * 32) * 4u;
#pragma unroll
        for (int j = 0; j < 8; ++j) cp16(vd + j * 16, vs + j * 4);
    };

    const int r = lane >> 2, cl = lane & 3;
    const int ql0 = w * 16 + r, ql1 = ql0 + 8;    // local query rows
    const int jmin = 512 - qb * 128;              // off >= jmin (key exists)
    const float scale = 1.0f / (float)HD;

    float accO[16][4];
#pragma unroll
    for (int nt = 0; nt < 16; ++nt)
#pragma unroll
        for (int i = 0; i < 4; ++i) accO[nt][i] = 0.f;
    float m0 = -3.0e38f, m1 = -3.0e38f, l0 = 0.f, l1 = 0.f;

    const int cstart = (qb < 4) ? (8 - 2 * qb) : 0;

    issueQ(); issueKV(cstart); CP_COMMIT();
    if (cstart + 1 < NCH) { issueKV(cstart + 1); CP_COMMIT(); }

#pragma unroll 1
    for (int c = cstart; c < NCH; ++c) {
        if (c + 1 < NCH) asm volatile("cp.async.wait_group 1;" ::: "memory");
        else             asm volatile("cp.async.wait_group 0;" ::: "memory");
        __syncthreads();

        // exact per-warp chunk skip: no (row, key) pair in this chunk can be valid
        // valid needs off > ql (some row) and off <= ql+512 (some row)
        const bool active = (c * 64 + 63 > w * 16) && (c * 64 <= w * 16 + 527);
        if (active) {
            const int s = c & 1;
            const float* Ksb = sm + SM_K + s * 64 * KSTR;
            const float* Vsb = sm + SM_V + s * 64 * VSTR;

            // ---- S = Q (128xHD) * Kchunk(64xHD)^T ----
            float accS[8][4];
#pragma unroll
            for (int nt = 0; nt < 8; ++nt)
#pragma unroll
                for (int i = 0; i < 4; ++i) accS[nt][i] = 0.f;
#pragma unroll
            for (int ks = 0; ks < 16; ++ks) {
                uint32_t a[4];
                const float* ab = sm + (w * 16 + r) * QSTR + ks * 8 + cl;
                a[0] = __float_as_uint(ab[0]);
                a[1] = __float_as_uint(ab[8 * QSTR]);
                a[2] = __float_as_uint(ab[4]);
                a[3] = __float_as_uint(ab[8 * QSTR + 4]);
#pragma unroll
                for (int nt = 0; nt < 8; ++nt) {
                    const float* bb = Ksb + (nt * 8 + r) * KSTR + ks * 8 + cl;
                    uint32_t b[2] = { __float_as_uint(bb[0]), __float_as_uint(bb[4]) };
                    mma_tf32(accS[nt], a, b);
                }
            }

            // ---- band mask + chunk row max ----
            float mc0 = -3.0e38f, mc1 = -3.0e38f;
#pragma unroll
            for (int nt = 0; nt < 8; ++nt) {
                const int off0 = c * 64 + nt * 8 + 2 * cl;
                const int off1 = off0 + 1;
                bool v00 = (off0 > ql0) && (off0 <= ql0 + 512) && (off0 >= jmin);
                bool v01 = (off1 > ql0) && (off1 <= ql0 + 512) && (off1 >= jmin);
                bool v10 = (off0 > ql1) && (off0 <= ql1 + 512) && (off0 >= jmin);
                bool v11 = (off1 > ql1) && (off1 <= ql1 + 512) && (off1 >= jmin);
                accS[nt][0] = v00 ? accS[nt][0] : -3.0e38f;
                accS[nt][1] = v01 ? accS[nt][1] : -3.0e38f;
                accS[nt][2] = v10 ? accS[nt][2] : -3.0e38f;
                accS[nt][3] = v11 ? accS[nt][3] : -3.0e38f;
                mc0 = fmaxf(mc0, fmaxf(accS[nt][0], accS[nt][1]));
                mc1 = fmaxf(mc1, fmaxf(accS[nt][2], accS[nt][3]));
            }
            mc0 = fmaxf(mc0, __shfl_xor_sync(0xffffffffu, mc0, 1));
            mc0 = fmaxf(mc0, __shfl_xor_sync(0xffffffffu, mc0, 2));
            mc1 = fmaxf(mc1, __shfl_xor_sync(0xffffffffu, mc1, 1));
            mc1 = fmaxf(mc1, __shfl_xor_sync(0xffffffffu, mc1, 2));

            // ---- online softmax update ----
            const float mn0 = fmaxf(m0, mc0), mn1 = fmaxf(m1, mc1);
            const float f0 = __expf((m0 - mn0) * scale);
            const float f1 = __expf((m1 - mn1) * scale);
            float s0 = 0.f, s1 = 0.f;
#pragma unroll
            for (int nt = 0; nt < 8; ++nt) {
                float e0 = (accS[nt][0] > -1.0e38f) ? __expf((accS[nt][0] - mn0) * scale) : 0.f;
                float e1 = (accS[nt][1] > -1.0e38f) ? __expf((accS[nt][1] - mn0) * scale) : 0.f;
                float e2 = (accS[nt][2] > -1.0e38f) ? __expf((accS[nt][2] - mn1) * scale) : 0.f;
                float e3 = (accS[nt][3] > -1.0e38f) ? __expf((accS[nt][3] - mn1) * scale) : 0.f;
                s0 += e0 + e1; s1 += e2 + e3;
                accS[nt][0] = to_tf32(e0); accS[nt][1] = to_tf32(e1);
                accS[nt][2] = to_tf32(e2); accS[nt][3] = to_tf32(e3);
            }
            s0 += __shfl_xor_sync(0xffffffffu, s0, 1);
            s0 += __shfl_xor_sync(0xffffffffu, s0, 2);
            s1 += __shfl_xor_sync(0xffffffffu, s1, 1);
            s1 += __shfl_xor_sync(0xffffffffu, s1, 2);
            l0 = l0 * f0 + s0; l1 = l1 * f1 + s1;
            m0 = mn0; m1 = mn1;
#pragma unroll
            for (int nt = 0; nt < 16; ++nt) {
                accO[nt][0] *= f0; accO[nt][1] *= f0;
                accO[nt][2] *= f1; accO[nt][3] *= f1;
            }

            // ---- O += P (128x64) * Vchunk (64xHD) ----
            const uint32_t srcl0 = (lane & ~3u) | ((uint32_t)(lane & 3) >> 1);
            const uint32_t srcl1 = srcl0 + 2;
            const bool odd = lane & 1;
#pragma unroll
            for (int ks = 0; ks < 8; ++ks) {
                float p0 = accS[ks][0], p1 = accS[ks][1];
                float p2 = accS[ks][2], p3 = accS[ks][3];
                float t00 = __shfl_sync(0xffffffffu, p0, srcl0);
                float t01 = __shfl_sync(0xffffffffu, p1, srcl0);
                float t10 = __shfl_sync(0xffffffffu, p2, srcl0);
                float t11 = __shfl_sync(0xffffffffu, p3, srcl0);
                float t20 = __shfl_sync(0xffffffffu, p0, srcl1);
                float t21 = __shfl_sync(0xffffffffu, p1, srcl1);
                float t30 = __shfl_sync(0xffffffffu, p2, srcl1);
                float t31 = __shfl_sync(0xffffffffu, p3, srcl1);
                uint32_t a[4];
                a[0] = __float_as_uint(odd ? t01 : t00);
                a[1] = __float_as_uint(odd ? t11 : t10);
                a[2] = __float_as_uint(odd ? t21 : t20);
                a[3] = __float_as_uint(odd ? t31 : t30);
#pragma unroll
                for (int nt = 0; nt < 16; ++nt) {
                    const float* bb = Vsb + (ks * 8 + cl) * VSTR + nt * 8 + r;
                    uint32_t b[2] = { __float_as_uint(bb[0]), __float_as_uint(bb[4 * VSTR]) };
                    mma_tf32(accO[nt], a, b);
                }
            }
        }
        __syncthreads();
        if (c + 2 < NCH) { issueKV(c + 2); CP_COMMIT(); }
    }

    // ---- finalize: O /= l, round, store ----
    const float inv0 = 1.0f / l0, inv1 = 1.0f / l1;
    float* O0 = g_attn + (size_t)(qb * 128 + ql0) * QDIM + h * HD;
    float* O1 = g_attn + (size_t)(qb * 128 + ql1) * QDIM + h * HD;
#pragma unroll
    for (int nt = 0; nt < 16; ++nt) {
        const int col = nt * 8 + 2 * cl;
        *(float2*)(O0 + col) = make_float2(to_tf32(accO[nt][0] * inv0),
                                           to_tf32(accO[nt][1] * inv0));
        *(float2*)(O1 + col) = make_float2(to_tf32(accO[nt][2] * inv1),
                                           to_tf32(accO[nt][3] * inv1));
    }
}

// ---------------- stage kernels ----------------
__global__ void zeropad_kernel() {
    int i = blockIdx.x * blockDim.x + threadIdx.x;
    if (i < WIN * KVDIM) { g_kpad[i] = 0.f; g_vpad[i] = 0.f; }
}

// one kernel rounds ALL inputs (h -> g_h; Wq/Wk/Wv -> g_wqkv concat; Wo -> g_wo)
#define N_H   (S_LEN * DMODEL)        /* 16777216 */
#define N_WQ  (DMODEL * QDIM)         /*  4194304 */
#define N_WKV (DMODEL * KVDIM)        /*  1048576 */
#define N_ALL (N_H + N_WQ + 2 * N_WKV + N_WQ)   /* 27262976 */
__global__ void round_all_kernel(const float* __restrict__ h,  const float* __restrict__ wq,
                                 const float* __restrict__ wk, const float* __restrict__ wv,
                                 const float* __restrict__ wo) {
    int i = (blockIdx.x * blockDim.x + threadIdx.x) * 4;
    const float* src;
    float* dst;
    if (i < N_H) {
        src = h + i; dst = g_h + i;
    } else if (i < N_H + N_WQ) {
        int j = i - N_H;
        src = wq + j; dst = g_wqkv + (size_t)(j >> 11) * NQKV + (j & 2047);
    } else if (i < N_H + N_WQ + N_WKV) {
        int j = i - N_H - N_WQ;
        src = wk + j; dst = g_wqkv + (size_t)(j >> 9) * NQKV + QDIM + (j & 511);
    } else if (i < N_H + N_WQ + 2 * N_WKV) {
        int j = i - N_H - N_WQ - N_WKV;
        src = wv + j; dst = g_wqkv + (size_t)(j >> 9) * NQKV + QDIM + KVDIM + (j & 511);
    } else {
        int j = i - N_H - N_WQ - 2 * N_WKV;
        src = wo + j; dst = g_wo + j;
    }
    float4 v = *(const float4*)src;
    v.x = to_tf32(v.x); v.y = to_tf32(v.y);
    v.z = to_tf32(v.z); v.w = to_tf32(v.w);
    *(float4*)dst = v;
}

// ---------------- launcher (graph-capturable: kernels only) ----------------
extern "C" void kernel_launch(void* const* d_in, const int* in_sizes, int n_in,
                              void* d_out, int out_size) {
    const float* hidden = (const float*)d_in[0];
    const float* Wq = (const float*)d_in[1];
    const float* Wk = (const float*)d_in[2];
    const float* Wv = (const float*)d_in[3];
    const float* Wo = (const float*)d_in[4];
    float* out = (float*)d_out;

    cudaFuncSetAttribute(fattn_kernel, cudaFuncAttributeMaxDynamicSharedMemorySize,
                         FA_SMEM_BYTES);
    cudaFuncSetAttribute(qkvproj_mma, cudaFuncAttributeMaxDynamicSharedMemorySize, GEMM_SMEM_BYTES);
    cudaFuncSetAttribute(oproj_mma,   cudaFuncAttributeMaxDynamicSharedMemorySize, GEMM_SMEM_BYTES);

    dim3 blk(256);
    // launch 0: round all inputs to tf32 (zero-mean rounding; removes truncation bias)
    round_all_kernel<<<N_ALL / 4 / 256, 256>>>(hidden, Wq, Wk, Wv, Wo);
    // launch 1: merged QKV projection
    qkvproj_mma<<<dim3(24, S_LEN / 128), blk, GEMM_SMEM_BYTES>>>();
    // zeropad touches kpad/vpad rows 0..511 only; projections write rows >= 512
    zeropad_kernel<<<(WIN * KVDIM + 255) / 256, 256>>>();
    fattn_kernel<<<dim3(S_LEN / 128, HQN), blk, FA_SMEM_BYTES>>>();            // (64,16)
    oproj_mma<<<dim3(DMODEL / 128, S_LEN / 128), blk, GEMM_SMEM_BYTES>>>(out); // (16,64)
}

// round 12
// speedup vs baseline: 1.5709x; 1.5709x over previous
#include <cuda_runtime.h>
#include <cstdint>
#include <math.h>

#define S_LEN  8192
#define DMODEL 2048
#define HQN    16
#define HKVN   4
#define HD     128
#define WIN    512
#define KVDIM  (HKVN * HD)        /* 512 */
#define QDIM   (HQN * HD)         /* 2048 */
#define NQKV   3072               /* concatenated QKV output cols */

// ---- GEMM tiling (R7/R10 proven config): 128x128 tile, K=16 chunks, 4-stage ----
#define ASTR   20                 /* A smem row stride (floats) */
#define BSTR   136                /* B smem row stride (floats) */
#define ASTG   (128 * ASTR)       /* 2560 floats per A stage */
#define BSTG   (16 * BSTR)        /* 2176 floats per B stage */
#define NSTAGE 4
#define GEMM_SMEM_BYTES (NSTAGE * (ASTG + BSTG) * 4)   /* 75776 B */

// ---------------- scratch (static device globals; no allocation) ----------------
__device__ float g_q[S_LEN * QDIM];                         // 64 MB (tf32)
__device__ float g_kpad[(S_LEN + WIN) * KVDIM];             // 17 MB (rows 0..511 zero)
__device__ float g_vpad[(S_LEN + WIN) * KVDIM];             // 17 MB
__device__ float g_attn[S_LEN * QDIM];                      // 64 MB
// tf32-rounded inputs
__device__ float g_h[S_LEN * DMODEL];                       // 64 MB
__device__ float g_wqkv[DMODEL * NQKV];                     // 24 MB (Wq|Wk|Wv concat)
__device__ float g_wo[QDIM * DMODEL];                       // 16 MB

// ---------------- helpers ----------------
__device__ __forceinline__ float to_tf32(float x) {
    uint32_t u;
    asm("cvt.rna.tf32.f32 %0, %1;" : "=r"(u) : "f"(x));
    return __uint_as_float(u);
}
__device__ __forceinline__ uint32_t smem_u32(const void* p) {
    uint32_t a;
    asm("{ .reg .u64 t; cvta.to.shared.u64 t, %1; cvt.u32.u64 %0, t; }" : "=r"(a) : "l"(p));
    return a;
}
__device__ __forceinline__ void cp16(uint32_t dst, const void* src) {
    asm volatile("cp.async.cg.shared.global [%0], [%1], 16;" :: "r"(dst), "l"(src) : "memory");
}
#define CP_COMMIT() asm volatile("cp.async.commit_group;" ::: "memory")
__device__ __forceinline__ void mma_tf32(float* c, const uint32_t* a, const uint32_t* b) {
    asm volatile(
        "mma.sync.aligned.m16n8k8.row.col.f32.tf32.tf32.f32 "
        "{%0,%1,%2,%3}, {%4,%5,%6,%7}, {%8,%9}, {%0,%1,%2,%3};"
        : "+f"(c[0]), "+f"(c[1]), "+f"(c[2]), "+f"(c[3])
        : "r"(a[0]), "r"(a[1]), "r"(a[2]), "r"(a[3]), "r"(b[0]), "r"(b[1]));
}

// ---------------- mma.sync tf32 128x128 GEMM tile, NN, 4-stage (R7/R10 core, verbatim) ----------------
// C tile rows by*128.., cols 0..127 of (C = A * B[:, bcol:bcol+128]); C pre-offset to its col.
// ROUND: round outputs to tf32 (when C feeds a later MMA as operand)
template <bool ROUND>
__device__ __forceinline__ void gemm_mma(
    const float* __restrict__ A, int lda,
    const float* __restrict__ B, int ldb, int bcol,
    float* __restrict__ C, int ldc,
    int K, int by)
{
    extern __shared__ float smdyn[];
    float* As = smdyn;                       // NSTAGE * ASTG floats
    float* Bs = smdyn + NSTAGE * ASTG;       // NSTAGE * BSTG floats

    const int tid = threadIdx.x;
    const int lane = tid & 31;
    const int w = tid >> 5;
    const int wm = (w & 3) * 32;
    const int wn = (w >> 2) * 64;

    const float* Ag = A + (size_t)(by * 128) * lda;
    const float* Bg = B + bcol;

    const uint32_t as_base = smem_u32(As);
    const uint32_t bs_base = smem_u32(Bs);

    const int arow = tid >> 1;
    const int acol = (tid & 1) * 8;
    const int bid = tid * 2;
    const int brow = bid >> 5;
    const int bcol2 = (bid & 31) * 4;

    float acc[2][8][4];
#pragma unroll
    for (int mt = 0; mt < 2; ++mt)
#pragma unroll
        for (int nt = 0; nt < 8; ++nt)
#pragma unroll
            for (int i = 0; i < 4; ++i) acc[mt][nt][i] = 0.f;

    const int nch = K >> 4;

    auto issue = [&](int c, int s) {
        const int k0 = c << 4;
        {
            const float* src = Ag + (size_t)arow * lda + k0 + acol;
            uint32_t d = as_base + (uint32_t)(s * ASTG + arow * ASTR + acol) * 4u;
            cp16(d, src);
            cp16(d + 16, src + 4);
        }
        {
            const float* src = Bg + (size_t)(k0 + brow) * ldb + bcol2;
            uint32_t d = bs_base + (uint32_t)(s * BSTG + brow * BSTR + bcol2) * 4u;
            cp16(d, src);
            cp16(d + 16, src + 4);
        }
        CP_COMMIT();
    };

    // prologue: stages 0..NSTAGE-2 in flight
#pragma unroll
    for (int c = 0; c < NSTAGE - 1; ++c)
        if (c < nch) issue(c, c);

    for (int c = 0; c < nch; ++c) {
        const int s = c & (NSTAGE - 1);
        asm volatile("cp.async.wait_group %0;" :: "n"(NSTAGE - 2) : "memory");
        __syncthreads();

        const float* Asb = As + s * ASTG;
        const float* Bsb = Bs + s * BSTG;
        const int r = lane >> 2, cc = lane & 3;
#pragma unroll
        for (int ks = 0; ks < 2; ++ks) {
            uint32_t a[2][4], b[8][2];
#pragma unroll
            for (int mt = 0; mt < 2; ++mt) {
                const float* ab = Asb + (wm + mt * 16 + r) * ASTR + ks * 8 + cc;
                a[mt][0] = __float_as_uint(ab[0]);
                a[mt][1] = __float_as_uint(ab[8 * ASTR]);
                a[mt][2] = __float_as_uint(ab[4]);
                a[mt][3] = __float_as_uint(ab[8 * ASTR + 4]);
            }
#pragma unroll
            for (int nt = 0; nt < 8; ++nt) {
                const float* bb = Bsb + (ks * 8 + cc) * BSTR + wn + nt * 8 + r;
                b[nt][0] = __float_as_uint(bb[0]);
                b[nt][1] = __float_as_uint(bb[4 * BSTR]);
            }
#pragma unroll
            for (int mt = 0; mt < 2; ++mt)
#pragma unroll
                for (int nt = 0; nt < 8; ++nt)
                    mma_tf32(acc[mt][nt], a[mt], b[nt]);
        }

        if (c + NSTAGE - 1 < nch) issue(c + NSTAGE - 1, (c + NSTAGE - 1) & (NSTAGE - 1));
        else CP_COMMIT();   // keep group count exact at the tail
    }

    float* Cb = C + (size_t)(by * 128) * ldc;
    const int r = lane >> 2, c2 = (lane & 3) * 2;
#pragma unroll
    for (int mt = 0; mt < 2; ++mt) {
        const int row = wm + mt * 16 + r;
#pragma unroll
        for (int nt = 0; nt < 8; ++nt) {
            const int col = wn + nt * 8 + c2;
            float v0 = acc[mt][nt][0], v1 = acc[mt][nt][1];
            float v2 = acc[mt][nt][2], v3 = acc[mt][nt][3];
            if (ROUND) { v0 = to_tf32(v0); v1 = to_tf32(v1); v2 = to_tf32(v2); v3 = to_tf32(v3); }
            *(float2*)(Cb + (size_t)row * ldc + col) = make_float2(v0, v1);
            *(float2*)(Cb + (size_t)(row + 8) * ldc + col) = make_float2(v2, v3);
        }
    }
}

// ---------------- merged QKV projection: one GEMM vs concatenated weights ----------------
__global__ __launch_bounds__(256)
void qkvproj_mma(void) {
    const int bx = blockIdx.x, by = blockIdx.y;
    float* C;
    int ldc;
    if (bx < 16)      { C = g_q + bx * 128;                                    ldc = QDIM; }
    else if (bx < 20) { C = g_kpad + (size_t)WIN * KVDIM + (bx - 16) * 128;    ldc = KVDIM; }
    else              { C = g_vpad + (size_t)WIN * KVDIM + (bx - 20) * 128;    ldc = KVDIM; }
    gemm_mma<true>(g_h, DMODEL, g_wqkv, NQKV, bx * 128, C, ldc, DMODEL, by);
}
__global__ __launch_bounds__(256)
void oproj_mma(float* __restrict__ out) {
    gemm_mma<false>(g_attn, QDIM, g_wo, DMODEL, blockIdx.x * 128,
                    out + blockIdx.x * 128, DMODEL, QDIM, blockIdx.y);
}

// ---------------- fused flash attention (band window, online softmax) ----------------
// grid (64 qblocks, 16 heads), 256 threads (8 warps x 16 query rows)
#define QSTR 132
#define KSTR 132
#define VSTR 136
#define SM_Q 0
#define SM_K (128 * QSTR)                       /* 16896 */
#define SM_V (SM_K + 2 * 64 * KSTR)             /* 33792 floats after SM_K */
#define FA_SMEM_FLOATS (SM_V + 2 * 64 * VSTR)   /* 51200 floats */
#define FA_SMEM_BYTES  (FA_SMEM_FLOATS * 4)     /* 204800 B */
#define NCH 10

__global__ __launch_bounds__(256, 1)
void fattn_kernel() {
    extern __shared__ float sm[];
    const int qb = blockIdx.x, h = blockIdx.y;
    const int tid = threadIdx.x, lane = tid & 31, w = tid >> 5;
    const uint32_t sbase = smem_u32(sm);

    const float* Qg = g_q + (size_t)(qb * 128) * QDIM + h * HD;
    const float* Kg = g_kpad + (size_t)(qb * 128) * KVDIM + (h >> 2) * HD;
    const float* Vg = g_vpad + (size_t)(qb * 128) * KVDIM + (h >> 2) * HD;

    const int qr = tid >> 1, qh = tid & 1;   // Q loader: row, half
    const int kr = tid >> 2, kq = tid & 3;   // K/V loader: row, quarter

    auto issueQ = [&]() {
        const float* src = Qg + (size_t)qr * QDIM + qh * 64;
        uint32_t d = sbase + (uint32_t)(qr * QSTR + qh * 64) * 4u;
#pragma unroll
        for (int j = 0; j < 8; ++j) {
            cp16(d + j * 32, src + j * 8);
            cp16(d + j * 32 + 16, src + j * 8 + 4);
        }
    };
    auto issueKV = [&](int c) {
        const int s = c & 1;
        const float* ks = Kg + (size_t)(c * 64 + kr) * KVDIM + kq * 32;
        uint32_t kd = sbase + (uint32_t)(SM_K + s * 64 * KSTR + kr * KSTR + kq * 32) * 4u;
#pragma unroll
        for (int j = 0; j < 8; ++j) cp16(kd + j * 16, ks + j * 4);
        const float* vs = Vg + (size_t)(c * 64 + kr) * KVDIM + kq * 32;
        uint32_t vd = sbase + (uint32_t)(SM_V + s * 64 * VSTR + kr * VSTR + kq * 32) * 4u;
#pragma unroll
        for (int j = 0; j < 8; ++j) cp16(vd + j * 16, vs + j * 4);
    };

    const int r = lane >> 2, cl = lane & 3;
    const int ql0 = w * 16 + r, ql1 = ql0 + 8;    // local query rows
    const int jmin = 512 - qb * 128;              // off >= jmin (key exists)
    const float scale = 1.0f / (float)HD;

    float accO[16][4];
#pragma unroll
    for (int nt = 0; nt < 16; ++nt)
#pragma unroll
        for (int i = 0; i < 4; ++i) accO[nt][i] = 0.f;
    float m0 = -3.0e38f, m1 = -3.0e38f, l0 = 0.f, l1 = 0.f;

    const int cstart = (qb < 4) ? (8 - 2 * qb) : 0;

    issueQ(); issueKV(cstart); CP_COMMIT();
    if (cstart + 1 < NCH) { issueKV(cstart + 1); CP_COMMIT(); }

#pragma unroll 1
    for (int c = cstart; c < NCH; ++c) {
        if (c + 1 < NCH) asm volatile("cp.async.wait_group 1;" ::: "memory");
        else             asm volatile("cp.async.wait_group 0;" ::: "memory");
        __syncthreads();

        // exact per-warp chunk skip: chunk is dead for this warp when every key is
        // <= all its query rows (c*64+63 <= w*16) or beyond every window (c*64 > w*16+527)
        const bool active = (c * 64 + 63 > w * 16) && (c * 64 <= w * 16 + 527);
        if (active) {
            const int s = c & 1;
            const float* Ksb = sm + SM_K + s * 64 * KSTR;
            const float* Vsb = sm + SM_V + s * 64 * VSTR;

            // ---- S = Q (128xHD) * Kchunk(64xHD)^T ----
            float accS[8][4];
#pragma unroll
            for (int nt = 0; nt < 8; ++nt)
#pragma unroll
                for (int i = 0; i < 4; ++i) accS[nt][i] = 0.f;
#pragma unroll
            for (int ks = 0; ks < 16; ++ks) {
                uint32_t a[4];
                const float* ab = sm + (w * 16 + r) * QSTR + ks * 8 + cl;
                a[0] = __float_as_uint(ab[0]);
                a[1] = __float_as_uint(ab[8 * QSTR]);
                a[2] = __float_as_uint(ab[4]);
                a[3] = __float_as_uint(ab[8 * QSTR + 4]);
#pragma unroll
                for (int nt = 0; nt < 8; ++nt) {
                    const float* bb = Ksb + (nt * 8 + r) * KSTR + ks * 8 + cl;
                    uint32_t b[2] = { __float_as_uint(bb[0]), __float_as_uint(bb[4]) };
                    mma_tf32(accS[nt], a, b);
                }
            }

            // ---- band mask + chunk row max ----
            float mc0 = -3.0e38f, mc1 = -3.0e38f;
#pragma unroll
            for (int nt = 0; nt < 8; ++nt) {
                const int off0 = c * 64 + nt * 8 + 2 * cl;
                const int off1 = off0 + 1;
                bool v00 = (off0 > ql0) && (off0 <= ql0 + 512) && (off0 >= jmin);
                bool v01 = (off1 > ql0) && (off1 <= ql0 + 512) && (off1 >= jmin);
                bool v10 = (off0 > ql1) && (off0 <= ql1 + 512) && (off0 >= jmin);
                bool v11 = (off1 > ql1) && (off1 <= ql1 + 512) && (off1 >= jmin);
                accS[nt][0] = v00 ? accS[nt][0] : -3.0e38f;
                accS[nt][1] = v01 ? accS[nt][1] : -3.0e38f;
                accS[nt][2] = v10 ? accS[nt][2] : -3.0e38f;
                accS[nt][3] = v11 ? accS[nt][3] : -3.0e38f;
                mc0 = fmaxf(mc0, fmaxf(accS[nt][0], accS[nt][1]));
                mc1 = fmaxf(mc1, fmaxf(accS[nt][2], accS[nt][3]));
            }
            mc0 = fmaxf(mc0, __shfl_xor_sync(0xffffffffu, mc0, 1));
            mc0 = fmaxf(mc0, __shfl_xor_sync(0xffffffffu, mc0, 2));
            mc1 = fmaxf(mc1, __shfl_xor_sync(0xffffffffu, mc1, 1));
            mc1 = fmaxf(mc1, __shfl_xor_sync(0xffffffffu, mc1, 2));

            // ---- online softmax update ----
            const float mn0 = fmaxf(m0, mc0), mn1 = fmaxf(m1, mc1);
            const float f0 = __expf((m0 - mn0) * scale);
            const float f1 = __expf((m1 - mn1) * scale);
            float s0 = 0.f, s1 = 0.f;
#pragma unroll
            for (int nt = 0; nt < 8; ++nt) {
                float e0 = (accS[nt][0] > -1.0e38f) ? __expf((accS[nt][0] - mn0) * scale) : 0.f;
                float e1 = (accS[nt][1] > -1.0e38f) ? __expf((accS[nt][1] - mn0) * scale) : 0.f;
                float e2 = (accS[nt][2] > -1.0e38f) ? __expf((accS[nt][2] - mn1) * scale) : 0.f;
                float e3 = (accS[nt][3] > -1.0e38f) ? __expf((accS[nt][3] - mn1) * scale) : 0.f;
                s0 += e0 + e1; s1 += e2 + e3;
                accS[nt][0] = to_tf32(e0); accS[nt][1] = to_tf32(e1);
                accS[nt][2] = to_tf32(e2); accS[nt][3] = to_tf32(e3);
            }
            s0 += __shfl_xor_sync(0xffffffffu, s0, 1);
            s0 += __shfl_xor_sync(0xffffffffu, s0, 2);
            s1 += __shfl_xor_sync(0xffffffffu, s1, 1);
            s1 += __shfl_xor_sync(0xffffffffu, s1, 2);
            l0 = l0 * f0 + s0; l1 = l1 * f1 + s1;
            m0 = mn0; m1 = mn1;
#pragma unroll
            for (int nt = 0; nt < 16; ++nt) {
                accO[nt][0] *= f0; accO[nt][1] *= f0;
                accO[nt][2] *= f1; accO[nt][3] *= f1;
            }

            // ---- O += P (128x64) * Vchunk (64xHD) ----
            const uint32_t srcl0 = (lane & ~3u) | ((uint32_t)(lane & 3) >> 1);
            const uint32_t srcl1 = srcl0 + 2;
            const bool odd = lane & 1;
#pragma unroll
            for (int ks = 0; ks < 8; ++ks) {
                float p0 = accS[ks][0], p1 = accS[ks][1];
                float p2 = accS[ks][2], p3 = accS[ks][3];
                float t00 = __shfl_sync(0xffffffffu, p0, srcl0);
                float t01 = __shfl_sync(0xffffffffu, p1, srcl0);
                float t10 = __shfl_sync(0xffffffffu, p2, srcl0);
                float t11 = __shfl_sync(0xffffffffu, p3, srcl0);
                float t20 = __shfl_sync(0xffffffffu, p0, srcl1);
                float t21 = __shfl_sync(0xffffffffu, p1, srcl1);
                float t30 = __shfl_sync(0xffffffffu, p2, srcl1);
                float t31 = __shfl_sync(0xffffffffu, p3, srcl1);
                uint32_t a[4];
                a[0] = __float_as_uint(odd ? t01 : t00);
                a[1] = __float_as_uint(odd ? t11 : t10);
                a[2] = __float_as_uint(odd ? t21 : t20);
                a[3] = __float_as_uint(odd ? t31 : t30);
#pragma unroll
                for (int nt = 0; nt < 16; ++nt) {
                    const float* bb = Vsb + (ks * 8 + cl) * VSTR + nt * 8 + r;
                    uint32_t b[2] = { __float_as_uint(bb[0]), __float_as_uint(bb[4 * VSTR]) };
                    mma_tf32(accO[nt], a, b);
                }
            }
        }
        __syncthreads();
        if (c + 2 < NCH) { issueKV(c + 2); CP_COMMIT(); }
    }

    // ---- finalize: O /= l, round, store ----
    const float inv0 = 1.0f / l0, inv1 = 1.0f / l1;
    float* O0 = g_attn + (size_t)(qb * 128 + ql0) * QDIM + h * HD;
    float* O1 = g_attn + (size_t)(qb * 128 + ql1) * QDIM + h * HD;
#pragma unroll
    for (int nt = 0; nt < 16; ++nt) {
        const int col = nt * 8 + 2 * cl;
        *(float2*)(O0 + col) = make_float2(to_tf32(accO[nt][0] * inv0),
                                           to_tf32(accO[nt][1] * inv0));
        *(float2*)(O1 + col) = make_float2(to_tf32(accO[nt][2] * inv1),
                                           to_tf32(accO[nt][3] * inv1));
    }
}

// ---------------- stage kernels ----------------
__global__ void zeropad_kernel() {
    int i = blockIdx.x * blockDim.x + threadIdx.x;
    if (i < WIN * KVDIM) { g_kpad[i] = 0.f; g_vpad[i] = 0.f; }
}

// one kernel rounds ALL inputs (h -> g_h; Wq/Wk/Wv -> g_wqkv concat; Wo -> g_wo)
#define N_H   (S_LEN * DMODEL)        /* 16777216 */
#define N_WQ  (DMODEL * QDIM)         /*  4194304 */
#define N_WKV (DMODEL * KVDIM)        /*  1048576 */
#define N_ALL (N_H + N_WQ + 2 * N_WKV + N_WQ)   /* 27262976 */
__global__ void round_all_kernel(const float* __restrict__ h,  const float* __restrict__ wq,
                                 const float* __restrict__ wk, const float* __restrict__ wv,
                                 const float* __restrict__ wo) {
    int i = (blockIdx.x * blockDim.x + threadIdx.x) * 4;
    const float* src;
    float* dst;
    if (i < N_H) {
        src = h + i; dst = g_h + i;
    } else if (i < N_H + N_WQ) {
        int j = i - N_H;
        src = wq + j; dst = g_wqkv + (size_t)(j >> 11) * NQKV + (j & 2047);
    } else if (i < N_H + N_WQ + N_WKV) {
        int j = i - N_H - N_WQ;
        src = wk + j; dst = g_wqkv + (size_t)(j >> 9) * NQKV + QDIM + (j & 511);
    } else if (i < N_H + N_WQ + 2 * N_WKV) {
        int j = i - N_H - N_WQ - N_WKV;
        src = wv + j; dst = g_wqkv + (size_t)(j >> 9) * NQKV + QDIM + KVDIM + (j & 511);
    } else {
        int j = i - N_H - N_WQ - 2 * N_WKV;
        src = wo + j; dst = g_wo + j;
    }
    float4 v = *(const float4*)src;
    v.x = to_tf32(v.x); v.y = to_tf32(v.y);
    v.z = to_tf32(v.z); v.w = to_tf32(v.w);
    *(float4*)dst = v;
}

// ---------------- launcher (graph-capturable: kernels only) ----------------
extern "C" void kernel_launch(void* const* d_in, const int* in_sizes, int n_in,
                              void* d_out, int out_size) {
    const float* hidden = (const float*)d_in[0];
    const float* Wq = (const float*)d_in[1];
    const float* Wk = (const float*)d_in[2];
    const float* Wv = (const float*)d_in[3];
    const float* Wo = (const float*)d_in[4];
    float* out = (float*)d_out;

    cudaFuncSetAttribute(fattn_kernel, cudaFuncAttributeMaxDynamicSharedMemorySize,
                         FA_SMEM_BYTES);
    cudaFuncSetAttribute(qkvproj_mma, cudaFuncAttributeMaxDynamicSharedMemorySize, GEMM_SMEM_BYTES);
    cudaFuncSetAttribute(oproj_mma,   cudaFuncAttributeMaxDynamicSharedMemorySize, GEMM_SMEM_BYTES);

    dim3 blk(256);
    // launch 0: round all inputs to tf32 (zero-mean rounding; removes truncation bias)
    round_all_kernel<<<N_ALL / 4 / 256, 256>>>(hidden, Wq, Wk, Wv, Wo);
    // launch 1: merged QKV projection
    qkvproj_mma<<<dim3(24, S_LEN / 128), blk, GEMM_SMEM_BYTES>>>();
    // zeropad touches kpad/vpad rows 0..511 only; projections write rows >= 512
    zeropad_kernel<<<(WIN * KVDIM + 255) / 256, 256>>>();
    fattn_kernel<<<dim3(S_LEN / 128, HQN), blk, FA_SMEM_BYTES>>>();            // (64,16)
    oproj_mma<<<dim3(DMODEL / 128, S_LEN / 128), blk, GEMM_SMEM_BYTES>>>(out); // (16,64)
}

// round 13
// speedup vs baseline: 1.6271x; 1.0358x over previous
#include <cuda_runtime.h>
#include <cstdint>
#include <math.h>

#define S_LEN  8192
#define DMODEL 2048
#define HQN    16
#define HKVN   4
#define HD     128
#define WIN    512
#define KVDIM  (HKVN * HD)        /* 512 */
#define QDIM   (HQN * HD)         /* 2048 */
#define NQKV   3072               /* concatenated QKV output cols */

// ---- GEMM tiling (R7/R10/R12 proven config): 128x128 tile, K=16 chunks, 4-stage ----
#define ASTR   20                 /* A smem row stride (floats) */
#define BSTR   136                /* B smem row stride (floats) */
#define ASTG   (128 * ASTR)       /* 2560 floats per A stage */
#define BSTG   (16 * BSTR)        /* 2176 floats per B stage */
#define NSTAGE 4
#define GEMM_SMEM_BYTES (NSTAGE * (ASTG + BSTG) * 4)   /* 75776 B */

// ---------------- scratch (static device globals; no allocation) ----------------
__device__ float g_q[S_LEN * QDIM];                         // 64 MB (tf32)
__device__ float g_kpad[(S_LEN + WIN) * KVDIM];             // 17 MB (rows 0..511 zero)
__device__ float g_vpad[(S_LEN + WIN) * KVDIM];             // 17 MB
__device__ float g_attn[S_LEN * QDIM];                      // 64 MB
// tf32-rounded inputs
__device__ float g_h[S_LEN * DMODEL];                       // 64 MB
__device__ float g_wqkv[DMODEL * NQKV];                     // 24 MB (Wq|Wk|Wv concat)
__device__ float g_wo[QDIM * DMODEL];                       // 16 MB

// ---------------- helpers ----------------
__device__ __forceinline__ float to_tf32(float x) {
    uint32_t u;
    asm("cvt.rna.tf32.f32 %0, %1;" : "=r"(u) : "f"(x));
    return __uint_as_float(u);
}
__device__ __forceinline__ uint32_t smem_u32(const void* p) {
    uint32_t a;
    asm("{ .reg .u64 t; cvta.to.shared.u64 t, %1; cvt.u32.u64 %0, t; }" : "=r"(a) : "l"(p));
    return a;
}
__device__ __forceinline__ void cp16(uint32_t dst, const void* src) {
    asm volatile("cp.async.cg.shared.global [%0], [%1], 16;" :: "r"(dst), "l"(src) : "memory");
}
#define CP_COMMIT() asm volatile("cp.async.commit_group;" ::: "memory")
__device__ __forceinline__ void mma_tf32(float* c, const uint32_t* a, const uint32_t* b) {
    asm volatile(
        "mma.sync.aligned.m16n8k8.row.col.f32.tf32.tf32.f32 "
        "{%0,%1,%2,%3}, {%4,%5,%6,%7}, {%8,%9}, {%0,%1,%2,%3};"
        : "+f"(c[0]), "+f"(c[1]), "+f"(c[2]), "+f"(c[3])
        : "r"(a[0]), "r"(a[1]), "r"(a[2]), "r"(a[3]), "r"(b[0]), "r"(b[1]));
}

// ---------------- mma.sync tf32 128x128 GEMM tile, NN, 4-stage (R12 core, verbatim) ----------------
template <bool ROUND>
__device__ __forceinline__ void gemm_mma(
    const float* __restrict__ A, int lda,
    const float* __restrict__ B, int ldb, int bcol,
    float* __restrict__ C, int ldc,
    int K, int by)
{
    extern __shared__ float smdyn[];
    float* As = smdyn;                       // NSTAGE * ASTG floats
    float* Bs = smdyn + NSTAGE * ASTG;       // NSTAGE * BSTG floats

    const int tid = threadIdx.x;
    const int lane = tid & 31;
    const int w = tid >> 5;
    const int wm = (w & 3) * 32;
    const int wn = (w >> 2) * 64;

    const float* Ag = A + (size_t)(by * 128) * lda;
    const float* Bg = B + bcol;

    const uint32_t as_base = smem_u32(As);
    const uint32_t bs_base = smem_u32(Bs);

    const int arow = tid >> 1;
    const int acol = (tid & 1) * 8;
    const int bid = tid * 2;
    const int brow = bid >> 5;
    const int bcol2 = (bid & 31) * 4;

    float acc[2][8][4];
#pragma unroll
    for (int mt = 0; mt < 2; ++mt)
#pragma unroll
        for (int nt = 0; nt < 8; ++nt)
#pragma unroll
            for (int i = 0; i < 4; ++i) acc[mt][nt][i] = 0.f;

    const int nch = K >> 4;

    auto issue = [&](int c, int s) {
        const int k0 = c << 4;
        {
            const float* src = Ag + (size_t)arow * lda + k0 + acol;
            uint32_t d = as_base + (uint32_t)(s * ASTG + arow * ASTR + acol) * 4u;
            cp16(d, src);
            cp16(d + 16, src + 4);
        }
        {
            const float* src = Bg + (size_t)(k0 + brow) * ldb + bcol2;
            uint32_t d = bs_base + (uint32_t)(s * BSTG + brow * BSTR + bcol2) * 4u;
            cp16(d, src);
            cp16(d + 16, src + 4);
        }
        CP_COMMIT();
    };

#pragma unroll
    for (int c = 0; c < NSTAGE - 1; ++c)
        if (c < nch) issue(c, c);

    for (int c = 0; c < nch; ++c) {
        const int s = c & (NSTAGE - 1);
        asm volatile("cp.async.wait_group %0;" :: "n"(NSTAGE - 2) : "memory");
        __syncthreads();

        const float* Asb = As + s * ASTG;
        const float* Bsb = Bs + s * BSTG;
        const int r = lane >> 2, cc = lane & 3;
#pragma unroll
        for (int ks = 0; ks < 2; ++ks) {
            uint32_t a[2][4], b[8][2];
#pragma unroll
            for (int mt = 0; mt < 2; ++mt) {
                const float* ab = Asb + (wm + mt * 16 + r) * ASTR + ks * 8 + cc;
                a[mt][0] = __float_as_uint(ab[0]);
                a[mt][1] = __float_as_uint(ab[8 * ASTR]);
                a[mt][2] = __float_as_uint(ab[4]);
                a[mt][3] = __float_as_uint(ab[8 * ASTR + 4]);
            }
#pragma unroll
            for (int nt = 0; nt < 8; ++nt) {
                const float* bb = Bsb + (ks * 8 + cc) * BSTR + wn + nt * 8 + r;
                b[nt][0] = __float_as_uint(bb[0]);
                b[nt][1] = __float_as_uint(bb[4 * BSTR]);
            }
#pragma unroll
            for (int mt = 0; mt < 2; ++mt)
#pragma unroll
                for (int nt = 0; nt < 8; ++nt)
                    mma_tf32(acc[mt][nt], a[mt], b[nt]);
        }

        if (c + NSTAGE - 1 < nch) issue(c + NSTAGE - 1, (c + NSTAGE - 1) & (NSTAGE - 1));
        else CP_COMMIT();   // keep group count exact at the tail
    }

    float* Cb = C + (size_t)(by * 128) * ldc;
    const int r = lane >> 2, c2 = (lane & 3) * 2;
#pragma unroll
    for (int mt = 0; mt < 2; ++mt) {
        const int row = wm + mt * 16 + r;
#pragma unroll
        for (int nt = 0; nt < 8; ++nt) {
            const int col = wn + nt * 8 + c2;
            float v0 = acc[mt][nt][0], v1 = acc[mt][nt][1];
            float v2 = acc[mt][nt][2], v3 = acc[mt][nt][3];
            if (ROUND) { v0 = to_tf32(v0); v1 = to_tf32(v1); v2 = to_tf32(v2); v3 = to_tf32(v3); }
            *(float2*)(Cb + (size_t)row * ldc + col) = make_float2(v0, v1);
            *(float2*)(Cb + (size_t)(row + 8) * ldc + col) = make_float2(v2, v3);
        }
    }
}

// ---------------- merged QKV projection: one GEMM vs concatenated weights ----------------
__global__ __launch_bounds__(256)
void qkvproj_mma(void) {
    const int bx = blockIdx.x, by = blockIdx.y;
    float* C;
    int ldc;
    if (bx < 16)      { C = g_q + bx * 128;                                    ldc = QDIM; }
    else if (bx < 20) { C = g_kpad + (size_t)WIN * KVDIM + (bx - 16) * 128;    ldc = KVDIM; }
    else              { C = g_vpad + (size_t)WIN * KVDIM + (bx - 20) * 128;    ldc = KVDIM; }
    gemm_mma<true>(g_h, DMODEL, g_wqkv, NQKV, bx * 128, C, ldc, DMODEL, by);
}
__global__ __launch_bounds__(256)
void oproj_mma(float* __restrict__ out) {
    gemm_mma<false>(g_attn, QDIM, g_wo, DMODEL, blockIdx.x * 128,
                    out + blockIdx.x * 128, DMODEL, QDIM, blockIdx.y);
}

// ---------------- fused flash attention v2: 32-key chunks, single-buffer K/V, 2 CTAs/SM ----------------
// grid (64 qblocks, 16 heads), 256 threads (8 warps x 16 query rows)
#define QSTR 132
#define KSTR 132
#define VSTR 136
#define SM_K (128 * QSTR)                       /* 16896 floats: Q 67.6 KB */
#define SM_V (SM_K + 32 * KSTR)                 /* + K 16.9 KB */
#define FA_SMEM_FLOATS (SM_V + 32 * VSTR)       /* + V 17.4 KB = 25472 floats */
#define FA_SMEM_BYTES  (FA_SMEM_FLOATS * 4)     /* 101888 B -> 2 CTAs/SM */
#define NCH 20

__global__ __launch_bounds__(256, 2)
void fattn_kernel() {
    extern __shared__ float sm[];
    const int qb = blockIdx.x, h = blockIdx.y;
    const int tid = threadIdx.x, lane = tid & 31, w = tid >> 5;
    const uint32_t sbase = smem_u32(sm);

    const float* Qg = g_q + (size_t)(qb * 128) * QDIM + h * HD;
    const float* Kg = g_kpad + (size_t)(qb * 128) * KVDIM + (h >> 2) * HD;
    const float* Vg = g_vpad + (size_t)(qb * 128) * KVDIM + (h >> 2) * HD;

    const int qr = tid >> 1, qh = tid & 1;   // Q loader: row, half
    const int kr = tid >> 3, kq = tid & 7;   // K/V loader: row 0..31, 16-float col block

    auto issueQ = [&]() {
        const float* src = Qg + (size_t)qr * QDIM + qh * 64;
        uint32_t d = sbase + (uint32_t)(qr * QSTR + qh * 64) * 4u;
#pragma unroll
        for (int j = 0; j < 8; ++j) {
            cp16(d + j * 32, src + j * 8);
            cp16(d + j * 32 + 16, src + j * 8 + 4);
        }
    };
    auto issueKV = [&](int c) {
        const float* ks = Kg + (size_t)(c * 32 + kr) * KVDIM + kq * 16;
        uint32_t kd = sbase + (uint32_t)(SM_K + kr * KSTR + kq * 16) * 4u;
        cp16(kd, ks); cp16(kd + 16, ks + 4); cp16(kd + 32, ks + 8); cp16(kd + 48, ks + 12);
        const float* vs = Vg + (size_t)(c * 32 + kr) * KVDIM + kq * 16;
        uint32_t vd = sbase + (uint32_t)(SM_V + kr * VSTR + kq * 16) * 4u;
        cp16(vd, vs); cp16(vd + 16, vs + 4); cp16(vd + 32, vs + 8); cp16(vd + 48, vs + 12);
    };

    const int r = lane >> 2, cl = lane & 3;
    const int ql0 = w * 16 + r, ql1 = ql0 + 8;    // local query rows
    const float scale = 1.0f / (float)HD;

    float accO[16][4];
#pragma unroll
    for (int nt = 0; nt < 16; ++nt)
#pragma unroll
        for (int i = 0; i < 4; ++i) accO[nt][i] = 0.f;
    float m0 = -3.0e38f, m1 = -3.0e38f, l0 = 0.f, l1 = 0.f;

    // first chunk containing any existing key (off >= jmin = 512 - qb*128)
    const int cstart = (qb < 4) ? (16 - 4 * qb) : 0;
    const int jmin = 512 - qb * 128;

    issueQ();

#pragma unroll 1
    for (int c = cstart; c < NCH; ++c) {
        __syncthreads();                 // previous chunk fully consumed by all warps
        issueKV(c); CP_COMMIT();
        asm volatile("cp.async.wait_group 0;" ::: "memory");
        __syncthreads();

        // exact per-warp chunk skip
        const bool active = (c * 32 + 31 > w * 16) && (c * 32 <= w * 16 + 527);
        if (active) {
            const float* Ksb = sm + SM_K;
            const float* Vsb = sm + SM_V;

            // ---- S = Q (128xHD) * Kchunk(32xHD)^T ----
            float accS[4][4];
#pragma unroll
            for (int nt = 0; nt < 4; ++nt)
#pragma unroll
                for (int i = 0; i < 4; ++i) accS[nt][i] = 0.f;
#pragma unroll
            for (int ks = 0; ks < 16; ++ks) {
                uint32_t a[4];
                const float* ab = sm + (w * 16 + r) * QSTR + ks * 8 + cl;
                a[0] = __float_as_uint(ab[0]);
                a[1] = __float_as_uint(ab[8 * QSTR]);
                a[2] = __float_as_uint(ab[4]);
                a[3] = __float_as_uint(ab[8 * QSTR + 4]);
#pragma unroll
                for (int nt = 0; nt < 4; ++nt) {
                    const float* bb = Ksb + (nt * 8 + r) * KSTR + ks * 8 + cl;
                    uint32_t b[2] = { __float_as_uint(bb[0]), __float_as_uint(bb[4]) };
                    mma_tf32(accS[nt], a, b);
                }
            }

            // ---- band mask + chunk row max ----
            float mc0 = -3.0e38f, mc1 = -3.0e38f;
#pragma unroll
            for (int nt = 0; nt < 4; ++nt) {
                const int off0 = c * 32 + nt * 8 + 2 * cl;
                const int off1 = off0 + 1;
                bool v00 = (off0 > ql0) && (off0 <= ql0 + 512) && (off0 >= jmin);
                bool v01 = (off1 > ql0) && (off1 <= ql0 + 512) && (off1 >= jmin);
                bool v10 = (off0 > ql1) && (off0 <= ql1 + 512) && (off0 >= jmin);
                bool v11 = (off1 > ql1) && (off1 <= ql1 + 512) && (off1 >= jmin);
                accS[nt][0] = v00 ? accS[nt][0] : -3.0e38f;
                accS[nt][1] = v01 ? accS[nt][1] : -3.0e38f;
                accS[nt][2] = v10 ? accS[nt][2] : -3.0e38f;
                accS[nt][3] = v11 ? accS[nt][3] : -3.0e38f;
                mc0 = fmaxf(mc0, fmaxf(accS[nt][0], accS[nt][1]));
                mc1 = fmaxf(mc1, fmaxf(accS[nt][2], accS[nt][3]));
            }
            mc0 = fmaxf(mc0, __shfl_xor_sync(0xffffffffu, mc0, 1));
            mc0 = fmaxf(mc0, __shfl_xor_sync(0xffffffffu, mc0, 2));
            mc1 = fmaxf(mc1, __shfl_xor_sync(0xffffffffu, mc1, 1));
            mc1 = fmaxf(mc1, __shfl_xor_sync(0xffffffffu, mc1, 2));

            // ---- online softmax update ----
            const float mn0 = fmaxf(m0, mc0), mn1 = fmaxf(m1, mc1);
            const float f0 = __expf((m0 - mn0) * scale);
            const float f1 = __expf((m1 - mn1) * scale);
            float s0 = 0.f, s1 = 0.f;
#pragma unroll
            for (int nt = 0; nt < 4; ++nt) {
                float e0 = (accS[nt][0] > -1.0e38f) ? __expf((accS[nt][0] - mn0) * scale) : 0.f;
                float e1 = (accS[nt][1] > -1.0e38f) ? __expf((accS[nt][1] - mn0) * scale) : 0.f;
                float e2 = (accS[nt][2] > -1.0e38f) ? __expf((accS[nt][2] - mn1) * scale) : 0.f;
                float e3 = (accS[nt][3] > -1.0e38f) ? __expf((accS[nt][3] - mn1) * scale) : 0.f;
                s0 += e0 + e1; s1 += e2 + e3;
                accS[nt][0] = to_tf32(e0); accS[nt][1] = to_tf32(e1);
                accS[nt][2] = to_tf32(e2); accS[nt][3] = to_tf32(e3);
            }
            s0 += __shfl_xor_sync(0xffffffffu, s0, 1);
            s0 += __shfl_xor_sync(0xffffffffu, s0, 2);
            s1 += __shfl_xor_sync(0xffffffffu, s1, 1);
            s1 += __shfl_xor_sync(0xffffffffu, s1, 2);
            l0 = l0 * f0 + s0; l1 = l1 * f1 + s1;
            m0 = mn0; m1 = mn1;
#pragma unroll
            for (int nt = 0; nt < 16; ++nt) {
                accO[nt][0] *= f0; accO[nt][1] *= f0;
                accO[nt][2] *= f1; accO[nt][3] *= f1;
            }

            // ---- O += P (128x32) * Vchunk (32xHD) ----
            const uint32_t srcl0 = (lane & ~3u) | ((uint32_t)(lane & 3) >> 1);
            const uint32_t srcl1 = srcl0 + 2;
            const bool odd = lane & 1;
#pragma unroll
            for (int ks = 0; ks < 4; ++ks) {
                // convert C-frag cols {2c,2c+1} -> A-frag cols {c, c+4} via shuffles
                float p0 = accS[ks][0], p1 = accS[ks][1];
                float p2 = accS[ks][2], p3 = accS[ks][3];
                float t00 = __shfl_sync(0xffffffffu, p0, srcl0);
                float t01 = __shfl_sync(0xffffffffu, p1, srcl0);
                float t10 = __shfl_sync(0xffffffffu, p2, srcl0);
                float t11 = __shfl_sync(0xffffffffu, p3, srcl0);
                float t20 = __shfl_sync(0xffffffffu, p0, srcl1);
                float t21 = __shfl_sync(0xffffffffu, p1, srcl1);
                float t30 = __shfl_sync(0xffffffffu, p2, srcl1);
                float t31 = __shfl_sync(0xffffffffu, p3, srcl1);
                uint32_t a[4];
                a[0] = __float_as_uint(odd ? t01 : t00);
                a[1] = __float_as_uint(odd ? t11 : t10);
                a[2] = __float_as_uint(odd ? t21 : t20);
                a[3] = __float_as_uint(odd ? t31 : t30);
#pragma unroll
                for (int nt = 0; nt < 16; ++nt) {
                    const float* bb = Vsb + (ks * 8 + cl) * VSTR + nt * 8 + r;
                    uint32_t b[2] = { __float_as_uint(bb[0]), __float_as_uint(bb[4 * VSTR]) };
                    mma_tf32(accO[nt], a, b);
                }
            }
        }
    }

    // ---- finalize: O /= l, round, store ----
    const float inv0 = 1.0f / l0, inv1 = 1.0f / l1;
    float* O0 = g_attn + (size_t)(qb * 128 + ql0) * QDIM + h * HD;
    float* O1 = g_attn + (size_t)(qb * 128 + ql1) * QDIM + h * HD;
#pragma unroll
    for (int nt = 0; nt < 16; ++nt) {
        const int col = nt * 8 + 2 * cl;
        *(float2*)(O0 + col) = make_float2(to_tf32(accO[nt][0] * inv0),
                                           to_tf32(accO[nt][1] * inv0));
        *(float2*)(O1 + col) = make_float2(to_tf32(accO[nt][2] * inv1),
                                           to_tf32(accO[nt][3] * inv1));
    }
}

// ---------------- stage kernels ----------------
__global__ void zeropad_kernel() {
    int i = blockIdx.x * blockDim.x + threadIdx.x;
    if (i < WIN * KVDIM) { g_kpad[i] = 0.f; g_vpad[i] = 0.f; }
}

// one kernel rounds ALL inputs (h -> g_h; Wq/Wk/Wv -> g_wqkv concat; Wo -> g_wo)
#define N_H   (S_LEN * DMODEL)        /* 16777216 */
#define N_WQ  (DMODEL * QDIM)         /*  4194304 */
#define N_WKV (DMODEL * KVDIM)        /*  1048576 */
#define N_ALL (N_H + N_WQ + 2 * N_WKV + N_WQ)   /* 27262976 */
__global__ void round_all_kernel(const float* __restrict__ h,  const float* __restrict__ wq,
                                 const float* __restrict__ wk, const float* __restrict__ wv,
                                 const float* __restrict__ wo) {
    int i = (blockIdx.x * blockDim.x + threadIdx.x) * 4;
    const float* src;
    float* dst;
    if (i < N_H) {
        src = h + i; dst = g_h + i;
    } else if (i < N_H + N_WQ) {
        int j = i - N_H;
        src = wq + j; dst = g_wqkv + (size_t)(j >> 11) * NQKV + (j & 2047);
    } else if (i < N_H + N_WQ + N_WKV) {
        int j = i - N_H - N_WQ;
        src = wk + j; dst = g_wqkv + (size_t)(j >> 9) * NQKV + QDIM + (j & 511);
    } else if (i < N_H + N_WQ + 2 * N_WKV) {
        int j = i - N_H - N_WQ - N_WKV;
        src = wv + j; dst = g_wqkv + (size_t)(j >> 9) * NQKV + QDIM + KVDIM + (j & 511);
    } else {
        int j = i - N_H - N_WQ - 2 * N_WKV;
        src = wo + j; dst = g_wo + j;
    }
    float4 v = *(const float4*)src;
    v.x = to_tf32(v.x); v.y = to_tf32(v.y);
    v.z = to_tf32(v.z); v.w = to_tf32(v.w);
    *(float4*)dst = v;
}

// ---------------- launcher (graph-capturable: kernels only) ----------------
extern "C" void kernel_launch(void* const* d_in, const int* in_sizes, int n_in,
                              void* d_out, int out_size) {
    const float* hidden = (const float*)d_in[0];
    const float* Wq = (const float*)d_in[1];
    const float* Wk = (const float*)d_in[2];
    const float* Wv = (const float*)d_in[3];
    const float* Wo = (const float*)d_in[4];
    float* out = (float*)d_out;

    cudaFuncSetAttribute(fattn_kernel, cudaFuncAttributeMaxDynamicSharedMemorySize,
                         FA_SMEM_BYTES);
    cudaFuncSetAttribute(qkvproj_mma, cudaFuncAttributeMaxDynamicSharedMemorySize, GEMM_SMEM_BYTES);
    cudaFuncSetAttribute(oproj_mma,   cudaFuncAttributeMaxDynamicSharedMemorySize, GEMM_SMEM_BYTES);

    dim3 blk(256);
    // launch 0: round all inputs to tf32 (zero-mean rounding; removes truncation bias)
    round_all_kernel<<<N_ALL / 4 / 256, 256>>>(hidden, Wq, Wk, Wv, Wo);
    // launch 1: merged QKV projection
    qkvproj_mma<<<dim3(24, S_LEN / 128), blk, GEMM_SMEM_BYTES>>>();
    // zeropad touches kpad/vpad rows 0..511 only; projections write rows >= 512
    zeropad_kernel<<<(WIN * KVDIM + 255) / 256, 256>>>();
    fattn_kernel<<<dim3(S_LEN / 128, HQN), blk, FA_SMEM_BYTES>>>();            // (64,16)
    oproj_mma<<<dim3(DMODEL / 128, S_LEN / 128), blk, GEMM_SMEM_BYTES>>>(out); // (16,64)
}